// round 3
// baseline (speedup 1.0000x reference)
#include <cuda_runtime.h>
#include <cuda_fp16.h>
#include <cstdint>

// Matern-3/2 Gram via mma.sync (HMMA) fp16 split-precision, fused epilogue.
// out[n,m] = sigma^2*(1+v)*exp(-v), v = sqrt3*sqrt(max(|x|^2+|z|^2-2x.z,1e-12))/ls
// X[8192,64] f32, Z[4096,64] f32 -> out[8192,4096] f32.

#define SQRT3F 1.7320508075688772f
constexpr int KD   = 64;
constexpr int BM   = 128;
constexpr int BN   = 128;
constexpr int NMAX = 8192;
constexpr int MMAX = 4096;

__device__ float g_rowsq[NMAX + MMAX];
__device__ __align__(16) __half g_xhi[NMAX * KD];
__device__ __align__(16) __half g_xlo[NMAX * KD];
__device__ __align__(16) __half g_zhi[MMAX * KD];
__device__ __align__(16) __half g_zlo[MMAX * KD];

__device__ __forceinline__ uint32_t smem_u32(const void* p) {
    uint32_t a;
    asm("{ .reg .u64 t; cvta.to.shared.u64 t, %1; cvt.u32.u64 %0, t; }"
        : "=r"(a) : "l"(p));
    return a;
}
#define SW128(o) ((o) ^ (((o) >> 3) & 0x70))

__device__ __forceinline__ void ldsm_x4(uint32_t r[4], uint32_t addr) {
    asm volatile("ldmatrix.sync.aligned.m8n8.x4.shared.b16 {%0,%1,%2,%3}, [%4];"
                 : "=r"(r[0]), "=r"(r[1]), "=r"(r[2]), "=r"(r[3])
                 : "r"(addr));
}
__device__ __forceinline__ void mma_f16(float c[4], const uint32_t a[4],
                                        uint32_t b0, uint32_t b1) {
    asm volatile(
        "mma.sync.aligned.m16n8k16.row.col.f32.f16.f16.f32 "
        "{%0,%1,%2,%3}, {%4,%5,%6,%7}, {%8,%9}, {%0,%1,%2,%3};"
        : "+f"(c[0]), "+f"(c[1]), "+f"(c[2]), "+f"(c[3])
        : "r"(a[0]), "r"(a[1]), "r"(a[2]), "r"(a[3]), "r"(b0), "r"(b1));
}

// ---------------- prologue kernels ----------------
__global__ void rowsq_kernel(const float* __restrict__ X,
                             const float* __restrict__ Z, int N, int M) {
    int i = blockIdx.x * blockDim.x + threadIdx.x;
    if (i >= N + M) return;
    const float4* r4 = (const float4*)((i < N) ? (X + (size_t)i * KD)
                                               : (Z + (size_t)(i - N) * KD));
    float s = 0.f;
#pragma unroll
    for (int k = 0; k < KD / 4; k++) {
        float4 v = r4[k];
        s += v.x * v.x + v.y * v.y + v.z * v.z + v.w * v.w;
    }
    g_rowsq[i] = s;
}

__global__ void split_kernel(const float* __restrict__ X,
                             const float* __restrict__ Z, int N, int M) {
    int idx = blockIdx.x * blockDim.x + threadIdx.x;   // one float4 each
    int nx4 = N * (KD / 4);
    int total4 = (N + M) * (KD / 4);
    if (idx >= total4) return;
    const float4* src;
    __half *hid, *lod;
    size_t e;
    if (idx < nx4) {
        src = (const float4*)X + idx; hid = g_xhi; lod = g_xlo;
        e = (size_t)idx * 4;
    } else {
        src = (const float4*)Z + (idx - nx4); hid = g_zhi; lod = g_zlo;
        e = (size_t)(idx - nx4) * 4;
    }
    float4 v = *src;
    __half h0 = __float2half_rn(v.x);
    __half h1 = __float2half_rn(v.y);
    __half h2 = __float2half_rn(v.z);
    __half h3 = __float2half_rn(v.w);
    __half l0 = __float2half_rn(v.x - __half2float(h0));
    __half l1 = __float2half_rn(v.y - __half2float(h1));
    __half l2 = __float2half_rn(v.z - __half2float(h2));
    __half l3 = __float2half_rn(v.w - __half2float(h3));
    ((__half2*)(hid + e))[0] = __half2(h0, h1);
    ((__half2*)(hid + e))[1] = __half2(h2, h3);
    ((__half2*)(lod + e))[0] = __half2(l0, l1);
    ((__half2*)(lod + e))[1] = __half2(l2, l3);
}

// ---------------- main HMMA kernel ----------------
// smem: 4 tiles of 128 rows x 64 f16 (=128B/row, SW128 swizzled), + z2 block
constexpr int SM_XHI = 0;
constexpr int SM_XLO = SM_XHI + 16384;
constexpr int SM_ZHI = SM_XLO + 16384;
constexpr int SM_ZLO = SM_ZHI + 16384;
constexpr int SM_Z2  = SM_ZLO + 16384;
constexpr int SM_TOTAL = SM_Z2 + BN * 4;   // 66048

__global__ __launch_bounds__(256) void matern_hmma_kernel(
    const float* __restrict__ sigma, const float* __restrict__ lengthscale,
    float* __restrict__ out, int N, int M)
{
    extern __shared__ __align__(1024) char smem[];
    const uint32_t smem_base = smem_u32(smem);
    const int tid  = threadIdx.x;
    const int wid  = tid >> 5;
    const int lane = tid & 31;
    const int wrow = wid & 1;          // 2 row groups of 64
    const int wcol = wid >> 1;         // 4 col groups of 32
    const int brow = blockIdx.y * BM;
    const int bcol = blockIdx.x * BN;

    // ---- load 4 f16 tiles with SW128 swizzle ----
    {
        const uint4* xg_hi = (const uint4*)g_xhi + (size_t)brow * 8;
        const uint4* xg_lo = (const uint4*)g_xlo + (size_t)brow * 8;
        const uint4* zg_hi = (const uint4*)g_zhi + (size_t)bcol * 8;
        const uint4* zg_lo = (const uint4*)g_zlo + (size_t)bcol * 8;
#pragma unroll
        for (int t = 0; t < 4; t++) {
            int li = tid + t * 256;           // 0..1023
            int r  = li >> 3;                 // row 0..127
            int c  = li & 7;                  // 16B chunk in row
            uint32_t so = SW128((uint32_t)(r * 128 + c * 16));
            *(uint4*)(smem + SM_XHI + so) = xg_hi[(size_t)r * 8 + c];
            *(uint4*)(smem + SM_XLO + so) = xg_lo[(size_t)r * 8 + c];
            *(uint4*)(smem + SM_ZHI + so) = zg_hi[(size_t)r * 8 + c];
            *(uint4*)(smem + SM_ZLO + so) = zg_lo[(size_t)r * 8 + c];
        }
        if (tid < BN)
            ((float*)(smem + SM_Z2))[tid] = g_rowsq[N + bcol + tid];
    }
    __syncthreads();

    // ---- per-thread ldmatrix base offsets ----
    // A group g: rows wrow*64 + g*16 + (lane&15); k-half = lane>>4
    uint32_t a_row_byte[4];
#pragma unroll
    for (int g = 0; g < 4; g++)
        a_row_byte[g] = (uint32_t)((wrow * 64 + g * 16 + (lane & 15)) * 128);
    const uint32_t a_kh = (uint32_t)((lane >> 4) * 16);
    // B group h (n16): rows wcol*32 + h*16 + (lane&7) + ((lane>>4)<<3); k-half = (lane>>3)&1
    uint32_t b_row_byte[2];
#pragma unroll
    for (int h = 0; h < 2; h++)
        b_row_byte[h] = (uint32_t)((wcol * 32 + h * 16 + (lane & 7) +
                                    ((lane >> 4) << 3)) * 128);
    const uint32_t b_kh = (uint32_t)(((lane >> 3) & 1) * 16);

    float acc[4][4][4];
#pragma unroll
    for (int g = 0; g < 4; g++)
#pragma unroll
        for (int h = 0; h < 4; h++)
#pragma unroll
            for (int e = 0; e < 4; e++) acc[g][h][e] = 0.f;

    const uint32_t a_base[3] = { smem_base + SM_XHI, smem_base + SM_XLO,
                                 smem_base + SM_XHI };
    const uint32_t b_base[3] = { smem_base + SM_ZHI, smem_base + SM_ZHI,
                                 smem_base + SM_ZLO };

#pragma unroll
    for (int p = 0; p < 3; p++) {
#pragma unroll
        for (int ks = 0; ks < 4; ks++) {
            const uint32_t kb = (uint32_t)(ks * 32);
            uint32_t a[4][4], b[2][4];
#pragma unroll
            for (int g = 0; g < 4; g++)
                ldsm_x4(a[g], a_base[p] + SW128(a_row_byte[g] + kb + a_kh));
#pragma unroll
            for (int h = 0; h < 2; h++)
                ldsm_x4(b[h], b_base[p] + SW128(b_row_byte[h] + kb + b_kh));
#pragma unroll
            for (int g = 0; g < 4; g++) {
#pragma unroll
                for (int h = 0; h < 4; h++)
                    mma_f16(acc[g][h], a[g], b[h >> 1][(h & 1) * 2],
                            b[h >> 1][(h & 1) * 2 + 1]);
            }
        }
    }

    // ---- fused Matern-3/2 epilogue (registers -> gmem) ----
    const float sg = sigma[0];
    const float s2 = sg * sg;
    const float kv = SQRT3F / lengthscale[0];
    const float* z2s = (const float*)(smem + SM_Z2);

    const int r0 = wrow * 64 + (lane >> 2);
    const int c0 = wcol * 32 + (lane & 3) * 2;

#pragma unroll
    for (int g = 0; g < 4; g++) {
#pragma unroll
        for (int sub = 0; sub < 2; sub++) {
            const int row = r0 + g * 16 + sub * 8;
            const float x2 = g_rowsq[brow + row];
            float* rowptr = out + (size_t)(brow + row) * (size_t)M + bcol;
#pragma unroll
            for (int h = 0; h < 4; h++) {
                const int col = c0 + h * 8;
                float2 o;
#pragma unroll
                for (int e = 0; e < 2; e++) {
                    float dot = acc[g][h][sub * 2 + e];
                    float sq = fmaxf(x2 + z2s[col + e] - 2.0f * dot, 1e-12f);
                    float dist = sq * __frsqrt_rn(sq);
                    float v = kv * dist;
                    ((float*)&o)[e] = s2 * (1.0f + v) * __expf(-v);
                }
                *(float2*)(rowptr + col) = o;
            }
        }
    }
}

extern "C" void kernel_launch(void* const* d_in, const int* in_sizes, int n_in,
                              void* d_out, int out_size) {
    const float* X   = (const float*)d_in[0];
    const float* Z   = (const float*)d_in[1];
    const float* sig = (const float*)d_in[2];
    const float* len = (const float*)d_in[3];
    float* out = (float*)d_out;

    int N = in_sizes[0] / KD;   // 8192
    int M = in_sizes[1] / KD;   // 4096

    int total = N + M;
    rowsq_kernel<<<(total + 255) / 256, 256>>>(X, Z, N, M);
    int total4 = total * (KD / 4);
    split_kernel<<<(total4 + 255) / 256, 256>>>(X, Z, N, M);

    cudaFuncSetAttribute(matern_hmma_kernel,
                         cudaFuncAttributeMaxDynamicSharedMemorySize, SM_TOTAL);
    dim3 grid(M / BN, N / BM);
    matern_hmma_kernel<<<grid, 256, SM_TOTAL>>>(sig, len, out, N, M);
}

// round 4
// speedup vs baseline: 1.5642x; 1.5642x over previous
#include <cuda_runtime.h>
#include <cuda_fp16.h>
#include <cstdint>

// Matern-3/2 Gram via mma.sync (HMMA) fp16 split-precision, fused epilogue.
// R4: 64x64 tiles / 128 threads for high occupancy; fused prologue.
// X[8192,64] f32, Z[4096,64] f32 -> out[8192,4096] f32.

#define SQRT3F 1.7320508075688772f
constexpr int KD   = 64;
constexpr int BM   = 64;
constexpr int BN   = 64;
constexpr int NMAX = 8192;
constexpr int MMAX = 4096;

__device__ float g_rowsq[NMAX + MMAX];
__device__ __align__(16) __half g_xhi[NMAX * KD];
__device__ __align__(16) __half g_xlo[NMAX * KD];
__device__ __align__(16) __half g_zhi[MMAX * KD];
__device__ __align__(16) __half g_zlo[MMAX * KD];

__device__ __forceinline__ uint32_t smem_u32(const void* p) {
    uint32_t a;
    asm("{ .reg .u64 t; cvta.to.shared.u64 t, %1; cvt.u32.u64 %0, t; }"
        : "=r"(a) : "l"(p));
    return a;
}
#define SW128(o) ((o) ^ (((o) >> 3) & 0x70))

__device__ __forceinline__ void ldsm_x4(uint32_t r[4], uint32_t addr) {
    asm volatile("ldmatrix.sync.aligned.m8n8.x4.shared.b16 {%0,%1,%2,%3}, [%4];"
                 : "=r"(r[0]), "=r"(r[1]), "=r"(r[2]), "=r"(r[3])
                 : "r"(addr));
}
__device__ __forceinline__ void mma_f16(float c[4], const uint32_t a[4],
                                        uint32_t b0, uint32_t b1) {
    asm volatile(
        "mma.sync.aligned.m16n8k16.row.col.f32.f16.f16.f32 "
        "{%0,%1,%2,%3}, {%4,%5,%6,%7}, {%8,%9}, {%0,%1,%2,%3};"
        : "+f"(c[0]), "+f"(c[1]), "+f"(c[2]), "+f"(c[3])
        : "r"(a[0]), "r"(a[1]), "r"(a[2]), "r"(a[3]), "r"(b0), "r"(b1));
}

// ---------------- fused prologue: warp per row ----------------
// computes |row|^2 and the fp16 hi/lo split in one pass over X and Z.
__global__ __launch_bounds__(256) void prep_kernel(
    const float* __restrict__ X, const float* __restrict__ Z, int N, int M)
{
    int gw   = (blockIdx.x * blockDim.x + threadIdx.x) >> 5;  // global warp = row
    int lane = threadIdx.x & 31;
    if (gw >= N + M) return;

    const float* row;
    __half *hid, *lod;
    if (gw < N) { row = X + (size_t)gw * KD;       hid = g_xhi + (size_t)gw * KD;       lod = g_xlo + (size_t)gw * KD; }
    else        { row = Z + (size_t)(gw - N) * KD; hid = g_zhi + (size_t)(gw - N) * KD; lod = g_zlo + (size_t)(gw - N) * KD; }

    float2 v = ((const float2*)row)[lane];
    __half h0 = __float2half_rn(v.x);
    __half h1 = __float2half_rn(v.y);
    __half l0 = __float2half_rn(v.x - __half2float(h0));
    __half l1 = __float2half_rn(v.y - __half2float(h1));
    ((__half2*)hid)[lane] = __half2(h0, h1);
    ((__half2*)lod)[lane] = __half2(l0, l1);

    float s = v.x * v.x + v.y * v.y;
#pragma unroll
    for (int off = 16; off > 0; off >>= 1)
        s += __shfl_xor_sync(0xFFFFFFFFu, s, off);
    if (lane == 0) g_rowsq[gw] = s;
}

// ---------------- main HMMA kernel: 64x64 tile, 4 warps ----------------
// smem: 4 tiles of 64 rows x 64 f16 (=128B/row, SW128), + z2 block
constexpr int SM_XHI = 0;
constexpr int SM_XLO = SM_XHI + 8192;
constexpr int SM_ZHI = SM_XLO + 8192;
constexpr int SM_ZLO = SM_ZHI + 8192;
constexpr int SM_Z2  = SM_ZLO + 8192;
constexpr int SM_TOTAL = SM_Z2 + BN * 4;   // 33024

__global__ __launch_bounds__(128) void matern_hmma_kernel(
    const float* __restrict__ sigma, const float* __restrict__ lengthscale,
    float* __restrict__ out, int N, int M)
{
    __shared__ __align__(1024) char smem[SM_TOTAL];
    const uint32_t smem_base = smem_u32(smem);
    const int tid  = threadIdx.x;
    const int wid  = tid >> 5;         // warp -> 16-row slice of the 64-row tile
    const int lane = tid & 31;
    const int brow = blockIdx.y * BM;
    const int bcol = blockIdx.x * BN;

    // ---- load 4 f16 tiles with SW128 swizzle (32KB total, 16 uint4/thread) ----
    {
        const uint4* xg_hi = (const uint4*)g_xhi + (size_t)brow * 8;
        const uint4* xg_lo = (const uint4*)g_xlo + (size_t)brow * 8;
        const uint4* zg_hi = (const uint4*)g_zhi + (size_t)bcol * 8;
        const uint4* zg_lo = (const uint4*)g_zlo + (size_t)bcol * 8;
#pragma unroll
        for (int t = 0; t < 4; t++) {
            int li = tid + t * 128;           // 0..511
            int r  = li >> 3;                 // row 0..63
            int c  = li & 7;                  // 16B chunk in row
            uint32_t so = SW128((uint32_t)(r * 128 + c * 16));
            *(uint4*)(smem + SM_XHI + so) = xg_hi[(size_t)r * 8 + c];
            *(uint4*)(smem + SM_XLO + so) = xg_lo[(size_t)r * 8 + c];
            *(uint4*)(smem + SM_ZHI + so) = zg_hi[(size_t)r * 8 + c];
            *(uint4*)(smem + SM_ZLO + so) = zg_lo[(size_t)r * 8 + c];
        }
        if (tid < BN)
            ((float*)(smem + SM_Z2))[tid] = g_rowsq[N + bcol + tid];
    }
    __syncthreads();

    // ---- per-thread ldmatrix base offsets ----
    // A: rows wid*16 + (lane&15), k-half (lane>>4)*16B
    const uint32_t a_row_byte = (uint32_t)((wid * 16 + (lane & 15)) * 128);
    const uint32_t a_kh = (uint32_t)((lane >> 4) * 16);
    // B group h (n16): rows h*16 + (lane&7) + ((lane>>4)<<3), k-half ((lane>>3)&1)*16B
    uint32_t b_row_byte[4];
#pragma unroll
    for (int h = 0; h < 4; h++)
        b_row_byte[h] = (uint32_t)((h * 16 + (lane & 7) + ((lane >> 4) << 3)) * 128);
    const uint32_t b_kh = (uint32_t)(((lane >> 3) & 1) * 16);

    float acc[8][4];
#pragma unroll
    for (int j = 0; j < 8; j++)
#pragma unroll
        for (int e = 0; e < 4; e++) acc[j][e] = 0.f;

    const uint32_t a_base[3] = { smem_base + SM_XHI, smem_base + SM_XLO,
                                 smem_base + SM_XHI };
    const uint32_t b_base[3] = { smem_base + SM_ZHI, smem_base + SM_ZHI,
                                 smem_base + SM_ZLO };

#pragma unroll
    for (int p = 0; p < 3; p++) {
#pragma unroll
        for (int ks = 0; ks < 4; ks++) {
            const uint32_t kb = (uint32_t)(ks * 32);
            uint32_t a[4], b[4][4];
            ldsm_x4(a, a_base[p] + SW128(a_row_byte + kb + a_kh));
#pragma unroll
            for (int h = 0; h < 4; h++)
                ldsm_x4(b[h], b_base[p] + SW128(b_row_byte[h] + kb + b_kh));
#pragma unroll
            for (int j = 0; j < 8; j++)
                mma_f16(acc[j], a, b[j >> 1][(j & 1) * 2],
                        b[j >> 1][(j & 1) * 2 + 1]);
        }
    }

    // ---- fused Matern-3/2 epilogue (registers -> gmem) ----
    const float sg = sigma[0];
    const float s2 = sg * sg;
    const float kv = SQRT3F / lengthscale[0];
    const float* z2s = (const float*)(smem + SM_Z2);

    const int r0 = wid * 16 + (lane >> 2);
    const int c0 = (lane & 3) * 2;

#pragma unroll
    for (int sub = 0; sub < 2; sub++) {
        const int row = r0 + sub * 8;
        const float x2 = g_rowsq[brow + row];
        float* rowptr = out + (size_t)(brow + row) * (size_t)M + bcol;
#pragma unroll
        for (int j = 0; j < 8; j++) {
            const int col = c0 + j * 8;
            float2 o;
#pragma unroll
            for (int e = 0; e < 2; e++) {
                float dot = acc[j][sub * 2 + e];
                float sq = fmaxf(x2 + z2s[col + e] - 2.0f * dot, 1e-12f);
                float dist = sq * __frsqrt_rn(sq);
                float v = kv * dist;
                ((float*)&o)[e] = s2 * (1.0f + v) * __expf(-v);
            }
            *(float2*)(rowptr + col) = o;
        }
    }
}

extern "C" void kernel_launch(void* const* d_in, const int* in_sizes, int n_in,
                              void* d_out, int out_size) {
    const float* X   = (const float*)d_in[0];
    const float* Z   = (const float*)d_in[1];
    const float* sig = (const float*)d_in[2];
    const float* len = (const float*)d_in[3];
    float* out = (float*)d_out;

    int N = in_sizes[0] / KD;   // 8192
    int M = in_sizes[1] / KD;   // 4096

    int totalwarps = N + M;                         // one warp per row
    prep_kernel<<<(totalwarps * 32 + 255) / 256, 256>>>(X, Z, N, M);

    dim3 grid(M / BN, N / BM);                      // (64, 128) = 8192 CTAs
    matern_hmma_kernel<<<grid, 128>>>(sig, len, out, N, M);
}

// round 5
// speedup vs baseline: 1.7411x; 1.1131x over previous
#include <cuda_runtime.h>
#include <cuda_fp16.h>
#include <cstdint>

// Matern-3/2 Gram via mma.sync (HMMA) fp16 split-precision, fused epilogue.
// R5: 32x32 warp tiles, shared hi/lo fragments, algebraic swizzle, occ=6 CTA/SM.
// X[8192,64] f32, Z[4096,64] f32 -> out[8192,4096] f32.

#define SQRT3F 1.7320508075688772f
constexpr int KD   = 64;
constexpr int BM   = 64;
constexpr int BN   = 64;
constexpr int NMAX = 8192;
constexpr int MMAX = 4096;

__device__ float g_rowsq[NMAX + MMAX];
__device__ __align__(16) __half g_xhi[NMAX * KD];
__device__ __align__(16) __half g_xlo[NMAX * KD];
__device__ __align__(16) __half g_zhi[MMAX * KD];
__device__ __align__(16) __half g_zlo[MMAX * KD];

__device__ __forceinline__ uint32_t smem_u32(const void* p) {
    uint32_t a;
    asm("{ .reg .u64 t; cvta.to.shared.u64 t, %1; cvt.u32.u64 %0, t; }"
        : "=r"(a) : "l"(p));
    return a;
}
#define SW128(o) ((o) ^ (((o) >> 3) & 0x70))

__device__ __forceinline__ void ldsm_x4(uint32_t r[4], uint32_t addr) {
    asm volatile("ldmatrix.sync.aligned.m8n8.x4.shared.b16 {%0,%1,%2,%3}, [%4];"
                 : "=r"(r[0]), "=r"(r[1]), "=r"(r[2]), "=r"(r[3])
                 : "r"(addr));
}
__device__ __forceinline__ void mma_f16(float c[4], const uint32_t a[4],
                                        uint32_t b0, uint32_t b1) {
    asm volatile(
        "mma.sync.aligned.m16n8k16.row.col.f32.f16.f16.f32 "
        "{%0,%1,%2,%3}, {%4,%5,%6,%7}, {%8,%9}, {%0,%1,%2,%3};"
        : "+f"(c[0]), "+f"(c[1]), "+f"(c[2]), "+f"(c[3])
        : "r"(a[0]), "r"(a[1]), "r"(a[2]), "r"(a[3]), "r"(b0), "r"(b1));
}

// ---------------- fused prologue: warp per row ----------------
__global__ __launch_bounds__(256) void prep_kernel(
    const float* __restrict__ X, const float* __restrict__ Z, int N, int M)
{
    int gw   = (blockIdx.x * blockDim.x + threadIdx.x) >> 5;  // global warp = row
    int lane = threadIdx.x & 31;
    if (gw >= N + M) return;

    const float* row;
    __half *hid, *lod;
    if (gw < N) { row = X + (size_t)gw * KD;       hid = g_xhi + (size_t)gw * KD;       lod = g_xlo + (size_t)gw * KD; }
    else        { row = Z + (size_t)(gw - N) * KD; hid = g_zhi + (size_t)(gw - N) * KD; lod = g_zlo + (size_t)(gw - N) * KD; }

    float2 v = ((const float2*)row)[lane];
    __half h0 = __float2half_rn(v.x);
    __half h1 = __float2half_rn(v.y);
    __half l0 = __float2half_rn(v.x - __half2float(h0));
    __half l1 = __float2half_rn(v.y - __half2float(h1));
    ((__half2*)hid)[lane] = __half2(h0, h1);
    ((__half2*)lod)[lane] = __half2(l0, l1);

    float s = v.x * v.x + v.y * v.y;
#pragma unroll
    for (int off = 16; off > 0; off >>= 1)
        s += __shfl_xor_sync(0xFFFFFFFFu, s, off);
    if (lane == 0) g_rowsq[gw] = s;
}

// ---------------- main HMMA kernel: 64x64 tile, 4 warps (2x2) ----------------
constexpr int SM_XHI = 0;
constexpr int SM_XLO = SM_XHI + 8192;
constexpr int SM_ZHI = SM_XLO + 8192;
constexpr int SM_ZLO = SM_ZHI + 8192;
constexpr int SM_Z2  = SM_ZLO + 8192;
constexpr int SM_TOTAL = SM_Z2 + BN * 4;   // 33024
constexpr int LO_OFF = 8192;               // hi -> lo tile delta (both X and Z)

__global__ __launch_bounds__(128, 6) void matern_hmma_kernel(
    const float* __restrict__ sigma, const float* __restrict__ lengthscale,
    float* __restrict__ out, int N, int M)
{
    __shared__ __align__(1024) char smem[SM_TOTAL];
    const uint32_t smem_base = smem_u32(smem);
    const int tid  = threadIdx.x;
    const int wid  = tid >> 5;
    const int lane = tid & 31;
    const int wrow = wid & 1;          // 2 row groups of 32
    const int wcol = wid >> 1;         // 2 col groups of 32
    const int brow = blockIdx.y * BM;
    const int bcol = blockIdx.x * BN;

    // ---- load 4 f16 tiles with SW128 swizzle (32KB total) ----
    {
        const uint4* xg_hi = (const uint4*)g_xhi + (size_t)brow * 8;
        const uint4* xg_lo = (const uint4*)g_xlo + (size_t)brow * 8;
        const uint4* zg_hi = (const uint4*)g_zhi + (size_t)bcol * 8;
        const uint4* zg_lo = (const uint4*)g_zlo + (size_t)bcol * 8;
#pragma unroll
        for (int t = 0; t < 4; t++) {
            int li = tid + t * 128;           // 0..511
            int r  = li >> 3;                 // row 0..63
            int c  = li & 7;                  // 16B chunk in row
            uint32_t so = SW128((uint32_t)(r * 128 + c * 16));
            *(uint4*)(smem + SM_XHI + so) = xg_hi[(size_t)r * 8 + c];
            *(uint4*)(smem + SM_XLO + so) = xg_lo[(size_t)r * 8 + c];
            *(uint4*)(smem + SM_ZHI + so) = zg_hi[(size_t)r * 8 + c];
            *(uint4*)(smem + SM_ZLO + so) = zg_lo[(size_t)r * 8 + c];
        }
        if (tid < BN)
            ((float*)(smem + SM_Z2))[tid] = g_rowsq[N + bcol + tid];
    }
    __syncthreads();

    // ---- per-thread addresses via algebraic swizzle ----
    // For row_byte % 128 == 0 and off < 128:
    //   SW128(row_byte + off) = row_byte + (off ^ ((row & 7) * 16))
    // and for all our fragment rows (row & 7) == (lane & 7).
    const uint32_t m = (uint32_t)((lane & 7) * 16);
    // A group g: row = wrow*32 + g*16 + (lane&15); k-half (lane>>4)*16B
    const uint32_t a_kh = (uint32_t)((lane >> 4) * 16);
    uint32_t a_base[2];
#pragma unroll
    for (int g = 0; g < 2; g++)
        a_base[g] = smem_base + SM_XHI +
                    (uint32_t)((wrow * 32 + g * 16 + (lane & 15)) * 128);
    // B group h: row = wcol*32 + h*16 + (lane&7) + ((lane>>4)<<3); k-half ((lane>>3)&1)*16B
    const uint32_t b_kh = (uint32_t)(((lane >> 3) & 1) * 16);
    uint32_t b_base[2];
#pragma unroll
    for (int h = 0; h < 2; h++)
        b_base[h] = smem_base + SM_ZHI +
                    (uint32_t)((wcol * 32 + h * 16 + (lane & 7) +
                                ((lane >> 4) << 3)) * 128);
    // in-row swizzled offsets per k-step
    uint32_t ka[4], kb[4];
#pragma unroll
    for (int ks = 0; ks < 4; ks++) {
        ka[ks] = ((uint32_t)(ks * 32) + a_kh) ^ m;
        kb[ks] = ((uint32_t)(ks * 32) + b_kh) ^ m;
    }

    float acc[2][4][4];
#pragma unroll
    for (int g = 0; g < 2; g++)
#pragma unroll
        for (int j = 0; j < 4; j++)
#pragma unroll
            for (int e = 0; e < 4; e++) acc[g][j][e] = 0.f;

    // ---- mainloop: 4 k-steps, fragments loaded once, 3 passes each ----
#pragma unroll
    for (int ks = 0; ks < 4; ks++) {
        uint32_t ah[2][4], al[2][4], bh[2][4], bl[2][4];
#pragma unroll
        for (int g = 0; g < 2; g++) {
            ldsm_x4(ah[g], a_base[g] + ka[ks]);
            ldsm_x4(al[g], a_base[g] + LO_OFF + ka[ks]);
        }
#pragma unroll
        for (int h = 0; h < 2; h++) {
            ldsm_x4(bh[h], b_base[h] + kb[ks]);
            ldsm_x4(bl[h], b_base[h] + LO_OFF + kb[ks]);
        }
#pragma unroll
        for (int g = 0; g < 2; g++)
#pragma unroll
            for (int j = 0; j < 4; j++) {
                const int hh = j >> 1, q = (j & 1) * 2;
                mma_f16(acc[g][j], ah[g], bh[hh][q], bh[hh][q + 1]);  // hi.hi
                mma_f16(acc[g][j], al[g], bh[hh][q], bh[hh][q + 1]);  // lo.hi
                mma_f16(acc[g][j], ah[g], bl[hh][q], bl[hh][q + 1]);  // hi.lo
            }
    }

    // ---- fused Matern-3/2 epilogue ----
    const float sg = sigma[0];
    const float s2 = sg * sg;
    const float kv = SQRT3F / lengthscale[0];
    const float* z2s = (const float*)(smem + SM_Z2);

#pragma unroll
    for (int g = 0; g < 2; g++) {
#pragma unroll
        for (int sub = 0; sub < 2; sub++) {
            const int row = wrow * 32 + g * 16 + (lane >> 2) + sub * 8;
            const float x2 = g_rowsq[brow + row];
            float* rowptr = out + (size_t)(brow + row) * (size_t)M + bcol;
#pragma unroll
            for (int j = 0; j < 4; j++) {
                const int col = wcol * 32 + j * 8 + (lane & 3) * 2;
                float2 o;
#pragma unroll
                for (int e = 0; e < 2; e++) {
                    float dot = acc[g][j][sub * 2 + e];
                    float sq = fmaxf(x2 + z2s[col + e] - 2.0f * dot, 1e-12f);
                    float dist = sq * __frsqrt_rn(sq);
                    float v = kv * dist;
                    ((float*)&o)[e] = s2 * (1.0f + v) * __expf(-v);
                }
                *(float2*)(rowptr + col) = o;
            }
        }
    }
}

extern "C" void kernel_launch(void* const* d_in, const int* in_sizes, int n_in,
                              void* d_out, int out_size) {
    const float* X   = (const float*)d_in[0];
    const float* Z   = (const float*)d_in[1];
    const float* sig = (const float*)d_in[2];
    const float* len = (const float*)d_in[3];
    float* out = (float*)d_out;

    int N = in_sizes[0] / KD;   // 8192
    int M = in_sizes[1] / KD;   // 4096

    int totalwarps = N + M;                         // one warp per row
    prep_kernel<<<(totalwarps * 32 + 255) / 256, 256>>>(X, Z, N, M);

    dim3 grid(M / BN, N / BM);                      // 8192 CTAs
    matern_hmma_kernel<<<grid, 128>>>(sig, len, out, N, M);
}